// round 10
// baseline (speedup 1.0000x reference)
#include <cuda_runtime.h>
#include <cuda_fp16.h>

// Problem constants (fixed by the reference)
#define N_NODES 100000
#define N_EDGES 50000
#define M_INC   1600000
#define D       64
#define DC4     16         // float4 chunks per f32 row
#define MH      (M_INC / 2)

// bit-cast helpers
__device__ __forceinline__ unsigned h2_as_u(__half2 h) {
    return *reinterpret_cast<unsigned*>(&h);
}
__device__ __forceinline__ __half2 u_as_h2(unsigned u) {
    return *reinterpret_cast<__half2*>(&u);
}

// ---------------------------------------------------------------------------
// Scratch (__device__ globals; zero-initialized at load).
// INVARIANT: g_Dn and g_Be are zero at every kernel_launch entry —
// k_recip restores g_Be, k_final restores g_Dn.
// ---------------------------------------------------------------------------
__device__ float  g_Dn[N_NODES];             // weighted node degree
__device__ float  g_Be[N_EDGES];             // edge cardinality (atomic target)
__device__ float  g_Ber[N_EDGES];            // 1/Be (read-only in stage2)
__device__ __half g_xh[(long)N_NODES * D];   // x in fp16
__device__ __half g_ef[(long)N_EDGES * D];   // raw edge feature sums, fp16
__device__ __half g_h [(long)N_NODES * D];   // unscaled node accumulator fp16

// ---------------------------------------------------------------------------
// K0 (prep): convert x->fp16, zero ef/h. No atomics.
// ---------------------------------------------------------------------------
__global__ void k_prep(const float* __restrict__ x) {
    long i = blockIdx.x * (long)blockDim.x + threadIdx.x;
    long stride = (long)gridDim.x * blockDim.x;

    const long XH8 = (long)N_NODES * D / 8;
    for (long j = i; j < XH8; j += stride) {
        float4 a = ((const float4*)x)[j * 2];
        float4 b = ((const float4*)x)[j * 2 + 1];
        uint4 u;
        u.x = h2_as_u(__floats2half2_rn(a.x, a.y));
        u.y = h2_as_u(__floats2half2_rn(a.z, a.w));
        u.z = h2_as_u(__floats2half2_rn(b.x, b.y));
        u.w = h2_as_u(__floats2half2_rn(b.z, b.w));
        ((uint4*)g_xh)[j] = u;
    }

    const long EF8 = (long)N_EDGES * D / 8;
    const long H8  = (long)N_NODES * D / 8;
    uint4 z = make_uint4(0u, 0u, 0u, 0u);
    for (long j = i; j < EF8; j += stride) ((uint4*)g_ef)[j] = z;
    for (long j = i; j < H8;  j += stride) ((uint4*)g_h)[j]  = z;
}

// ---------------------------------------------------------------------------
// K1: stage 1 — scatter ef[e] += xh[n] (raw). 4 threads per incidence pair:
// thread t -> 32B chunk c = t&3, incidences m0 = t>>2 and m1 = m0 + M/2.
// Each thread: 4 LDG.128 gathers + 4 vector REDG (high MLP).
// Lane c==0 also does the Be count and weighted Dn atomics (ride in the
// shadow of the feature-REDG serialization).
// ---------------------------------------------------------------------------
__global__ void k_stage1(const int* __restrict__ ni, const int* __restrict__ ei,
                         const float* __restrict__ w) {
    int t = blockIdx.x * blockDim.x + threadIdx.x;
    if (t >= MH * 4) return;
    int c  = t & 3;          // 32B chunk -> uint4 indices 2c, 2c+1
    int m0 = t >> 2;
    int m1 = m0 + MH;

    int n0 = __ldg(&ni[m0]);
    int e0 = __ldg(&ei[m0]);
    int n1 = __ldg(&ni[m1]);
    int e1 = __ldg(&ei[m1]);

    const uint4* xr0 = &((const uint4*)g_xh)[(long)n0 * 8 + c * 2];
    const uint4* xr1 = &((const uint4*)g_xh)[(long)n1 * 8 + c * 2];
    uint4 a0 = __ldg(xr0);
    uint4 b0 = __ldg(xr0 + 1);
    uint4 a1 = __ldg(xr1);
    uint4 b1 = __ldg(xr1 + 1);

    __half* d0 = &g_ef[(long)e0 * D + c * 16];
    __half* d1 = &g_ef[(long)e1 * D + c * 16];
    asm volatile("red.global.add.noftz.v4.f16x2 [%0], {%1,%2,%3,%4};"
                 :: "l"(d0), "r"(a0.x), "r"(a0.y), "r"(a0.z), "r"(a0.w) : "memory");
    asm volatile("red.global.add.noftz.v4.f16x2 [%0], {%1,%2,%3,%4};"
                 :: "l"(d0 + 8), "r"(b0.x), "r"(b0.y), "r"(b0.z), "r"(b0.w) : "memory");
    asm volatile("red.global.add.noftz.v4.f16x2 [%0], {%1,%2,%3,%4};"
                 :: "l"(d1), "r"(a1.x), "r"(a1.y), "r"(a1.z), "r"(a1.w) : "memory");
    asm volatile("red.global.add.noftz.v4.f16x2 [%0], {%1,%2,%3,%4};"
                 :: "l"(d1 + 8), "r"(b1.x), "r"(b1.y), "r"(b1.z), "r"(b1.w) : "memory");

    if (c == 0) {
        float w0 = __ldg(&w[e0]);
        float w1 = __ldg(&w[e1]);
        atomicAdd(&g_Be[e0], 1.0f);
        atomicAdd(&g_Be[e1], 1.0f);
        atomicAdd(&g_Dn[n0], w0);
        atomicAdd(&g_Dn[n1], w1);
    }
}

// ---------------------------------------------------------------------------
// K2: tiny recip — Ber[e] = 1/Be[e] (safe), restore Be[e] = 0.
// One thread per edge; single reader/writer, race-free.
// ---------------------------------------------------------------------------
__global__ void k_recip() {
    int e = blockIdx.x * blockDim.x + threadIdx.x;
    if (e >= N_EDGES) return;
    float b = g_Be[e];
    g_Ber[e] = (b > 0.f) ? (1.0f / b) : 0.f;
    g_Be[e] = 0.f;   // restore invariant for next call
}

// ---------------------------------------------------------------------------
// K3: stage 2 — h[n] += Ber[e] * ef[e]  (scale folded into the gather path).
// Same 4-threads-per-incidence mapping as stage 1.
// ---------------------------------------------------------------------------
__global__ void k_stage2(const int* __restrict__ ni, const int* __restrict__ ei) {
    int t = blockIdx.x * blockDim.x + threadIdx.x;
    if (t >= MH * 4) return;
    int c  = t & 3;
    int m0 = t >> 2;
    int m1 = m0 + MH;

    int n0 = __ldg(&ni[m0]);
    int e0 = __ldg(&ei[m0]);
    int n1 = __ldg(&ni[m1]);
    int e1 = __ldg(&ei[m1]);

    __half2 r0 = __float2half2_rn(g_Ber[e0]);
    __half2 r1 = __float2half2_rn(g_Ber[e1]);

    const uint4* er0 = &((const uint4*)g_ef)[(long)e0 * 8 + c * 2];
    const uint4* er1 = &((const uint4*)g_ef)[(long)e1 * 8 + c * 2];
    uint4 a0 = __ldg(er0);
    uint4 b0 = __ldg(er0 + 1);
    uint4 a1 = __ldg(er1);
    uint4 b1 = __ldg(er1 + 1);

    a0.x = h2_as_u(__hmul2(u_as_h2(a0.x), r0));
    a0.y = h2_as_u(__hmul2(u_as_h2(a0.y), r0));
    a0.z = h2_as_u(__hmul2(u_as_h2(a0.z), r0));
    a0.w = h2_as_u(__hmul2(u_as_h2(a0.w), r0));
    b0.x = h2_as_u(__hmul2(u_as_h2(b0.x), r0));
    b0.y = h2_as_u(__hmul2(u_as_h2(b0.y), r0));
    b0.z = h2_as_u(__hmul2(u_as_h2(b0.z), r0));
    b0.w = h2_as_u(__hmul2(u_as_h2(b0.w), r0));
    a1.x = h2_as_u(__hmul2(u_as_h2(a1.x), r1));
    a1.y = h2_as_u(__hmul2(u_as_h2(a1.y), r1));
    a1.z = h2_as_u(__hmul2(u_as_h2(a1.z), r1));
    a1.w = h2_as_u(__hmul2(u_as_h2(a1.w), r1));
    b1.x = h2_as_u(__hmul2(u_as_h2(b1.x), r1));
    b1.y = h2_as_u(__hmul2(u_as_h2(b1.y), r1));
    b1.z = h2_as_u(__hmul2(u_as_h2(b1.z), r1));
    b1.w = h2_as_u(__hmul2(u_as_h2(b1.w), r1));

    __half* d0 = &g_h[(long)n0 * D + c * 16];
    __half* d1 = &g_h[(long)n1 * D + c * 16];
    asm volatile("red.global.add.noftz.v4.f16x2 [%0], {%1,%2,%3,%4};"
                 :: "l"(d0), "r"(a0.x), "r"(a0.y), "r"(a0.z), "r"(a0.w) : "memory");
    asm volatile("red.global.add.noftz.v4.f16x2 [%0], {%1,%2,%3,%4};"
                 :: "l"(d0 + 8), "r"(b0.x), "r"(b0.y), "r"(b0.z), "r"(b0.w) : "memory");
    asm volatile("red.global.add.noftz.v4.f16x2 [%0], {%1,%2,%3,%4};"
                 :: "l"(d1), "r"(a1.x), "r"(a1.y), "r"(a1.z), "r"(a1.w) : "memory");
    asm volatile("red.global.add.noftz.v4.f16x2 [%0], {%1,%2,%3,%4};"
                 :: "l"(d1 + 8), "r"(b1.x), "r"(b1.y), "r"(b1.z), "r"(b1.w) : "memory");
}

// ---------------------------------------------------------------------------
// K4: final — out = 0.5*x + (0.5/Dn)*h, then restore Dn[node]=0.
// 16 lanes per node (one warp), lane-0 zero-store after all lanes' load.
// ---------------------------------------------------------------------------
__global__ void k_final(const float* __restrict__ x, float* __restrict__ out) {
    int t = blockIdx.x * blockDim.x + threadIdx.x;
    if (t >= N_NODES * DC4) return;
    int node = t >> 4;
    float dnv = g_Dn[node];
    float dn = (dnv > 0.f) ? (0.5f / dnv) : 0.f;

    float4 xv = ((const float4*)x)[t];
    uint2 hu = ((const uint2*)g_h)[t];
    float2 h01 = __half22float2(u_as_h2(hu.x));
    float2 h23 = __half22float2(u_as_h2(hu.y));

    float4 o;
    o.x = 0.5f * xv.x + dn * h01.x;
    o.y = 0.5f * xv.y + dn * h01.y;
    o.z = 0.5f * xv.z + dn * h23.x;
    o.w = 0.5f * xv.w + dn * h23.y;
    ((float4*)out)[t] = o;

    if ((t & 15) == 0) g_Dn[node] = 0.f;   // restore invariant for next call
}

// ---------------------------------------------------------------------------
extern "C" void kernel_launch(void* const* d_in, const int* in_sizes, int n_in,
                              void* d_out, int out_size) {
    const float* x  = (const float*)d_in[0];
    const int*   ni = (const int*)d_in[1];
    const int*   ei = (const int*)d_in[2];
    const float* w  = (const float*)d_in[3];
    float* out = (float*)d_out;

    const int T = 256;
    int stage_threads = MH * 4;                   // 3.2M threads

    k_prep<<<2048, T>>>(x);
    k_stage1<<<(stage_threads + T - 1) / T, T>>>(ni, ei, w);
    k_recip<<<(N_EDGES + T - 1) / T, T>>>();
    k_stage2<<<(stage_threads + T - 1) / T, T>>>(ni, ei);
    k_final<<<(N_NODES * DC4 + T - 1) / T, T>>>(x, out);
}

// round 11
// speedup vs baseline: 1.3119x; 1.3119x over previous
#include <cuda_runtime.h>
#include <cuda_fp16.h>

// Problem constants (fixed by the reference)
#define N_NODES 100000
#define N_EDGES 50000
#define M_INC   1600000
#define D       64
#define DCH     8          // 16B chunks per fp16 row (8 lanes cover one row)
#define DC4     16         // float4 chunks per f32 row
#define MH      (M_INC / 2)

// bit-cast helpers
__device__ __forceinline__ unsigned h2_as_u(__half2 h) {
    return *reinterpret_cast<unsigned*>(&h);
}
__device__ __forceinline__ __half2 u_as_h2(unsigned u) {
    return *reinterpret_cast<__half2*>(&u);
}

// ---------------------------------------------------------------------------
// Scratch (__device__ globals; zero-initialized at load).
// INVARIANT: g_Dn and g_Be are zero at every kernel_launch entry —
// k_recip restores g_Be, k_final restores g_Dn.
// ---------------------------------------------------------------------------
__device__ float  g_Dn[N_NODES];             // weighted node degree
__device__ float  g_Be[N_EDGES];             // edge cardinality (atomic target)
__device__ float  g_Ber[N_EDGES];            // 1/Be (read-only in stage2)
__device__ __half g_xh[(long)N_NODES * D];   // x in fp16
__device__ __half g_ef[(long)N_EDGES * D];   // raw edge feature sums, fp16
__device__ __half g_h [(long)N_NODES * D];   // unscaled node accumulator fp16

// ---------------------------------------------------------------------------
// K0 (prep): convert x->fp16, zero ef/h. No atomics.
// ---------------------------------------------------------------------------
__global__ void k_prep(const float* __restrict__ x) {
    long i = blockIdx.x * (long)blockDim.x + threadIdx.x;
    long stride = (long)gridDim.x * blockDim.x;

    const long XH8 = (long)N_NODES * D / 8;
    for (long j = i; j < XH8; j += stride) {
        float4 a = ((const float4*)x)[j * 2];
        float4 b = ((const float4*)x)[j * 2 + 1];
        uint4 u;
        u.x = h2_as_u(__floats2half2_rn(a.x, a.y));
        u.y = h2_as_u(__floats2half2_rn(a.z, a.w));
        u.z = h2_as_u(__floats2half2_rn(b.x, b.y));
        u.w = h2_as_u(__floats2half2_rn(b.z, b.w));
        ((uint4*)g_xh)[j] = u;
    }

    const long EF8 = (long)N_EDGES * D / 8;
    const long H8  = (long)N_NODES * D / 8;
    uint4 z = make_uint4(0u, 0u, 0u, 0u);
    for (long j = i; j < EF8; j += stride) ((uint4*)g_ef)[j] = z;
    for (long j = i; j < H8;  j += stride) ((uint4*)g_h)[j]  = z;
}

// ---------------------------------------------------------------------------
// K1: stage 1 — scatter ef[e] += xh[n] (raw fp16x2 vector REDG).
// thread t -> 16B chunk c = t&7, incidences m0 = t>>3 and m1 = m0 + M/2.
// 8 consecutive lanes cover one 128B row contiguously (coalesced).
// Lane c==0 also does the Be count and weighted Dn atomics (these ride in
// the shadow of the feature-REDG per-address serialization).
// ---------------------------------------------------------------------------
__global__ void k_stage1(const int* __restrict__ ni, const int* __restrict__ ei,
                         const float* __restrict__ w) {
    int t = blockIdx.x * blockDim.x + threadIdx.x;
    if (t >= MH * DCH) return;
    int c  = t & 7;
    int m0 = t >> 3;
    int m1 = m0 + MH;

    int n0 = __ldg(&ni[m0]);
    int e0 = __ldg(&ei[m0]);
    int n1 = __ldg(&ni[m1]);
    int e1 = __ldg(&ei[m1]);

    uint4 u0 = __ldg(&((const uint4*)g_xh)[(long)n0 * DCH + c]);
    uint4 u1 = __ldg(&((const uint4*)g_xh)[(long)n1 * DCH + c]);

    __half* d0 = &g_ef[(long)e0 * D + c * 8];
    __half* d1 = &g_ef[(long)e1 * D + c * 8];
    asm volatile("red.global.add.noftz.v4.f16x2 [%0], {%1,%2,%3,%4};"
                 :: "l"(d0), "r"(u0.x), "r"(u0.y), "r"(u0.z), "r"(u0.w) : "memory");
    asm volatile("red.global.add.noftz.v4.f16x2 [%0], {%1,%2,%3,%4};"
                 :: "l"(d1), "r"(u1.x), "r"(u1.y), "r"(u1.z), "r"(u1.w) : "memory");

    if (c == 0) {
        float w0 = __ldg(&w[e0]);
        float w1 = __ldg(&w[e1]);
        atomicAdd(&g_Be[e0], 1.0f);
        atomicAdd(&g_Be[e1], 1.0f);
        atomicAdd(&g_Dn[n0], w0);
        atomicAdd(&g_Dn[n1], w1);
    }
}

// ---------------------------------------------------------------------------
// K2: tiny recip — Ber[e] = 1/Be[e] (safe), restore Be[e] = 0.
// One thread per edge; single reader/writer, race-free.
// ---------------------------------------------------------------------------
__global__ void k_recip() {
    int e = blockIdx.x * blockDim.x + threadIdx.x;
    if (e >= N_EDGES) return;
    float b = g_Be[e];
    g_Ber[e] = (b > 0.f) ? (1.0f / b) : 0.f;
    g_Be[e] = 0.f;   // restore invariant for next call
}

// ---------------------------------------------------------------------------
// K3: stage 2 — h[n] += Ber[e] * ef[e] (scale folded into the gather path).
// Same 8-lanes-per-row mapping as stage 1; Ber[e] broadcasts across the
// 8 lanes of an edge (L1 hit).
// ---------------------------------------------------------------------------
__global__ void k_stage2(const int* __restrict__ ni, const int* __restrict__ ei) {
    int t = blockIdx.x * blockDim.x + threadIdx.x;
    if (t >= MH * DCH) return;
    int c  = t & 7;
    int m0 = t >> 3;
    int m1 = m0 + MH;

    int n0 = __ldg(&ni[m0]);
    int e0 = __ldg(&ei[m0]);
    int n1 = __ldg(&ni[m1]);
    int e1 = __ldg(&ei[m1]);

    __half2 r0 = __float2half2_rn(g_Ber[e0]);
    __half2 r1 = __float2half2_rn(g_Ber[e1]);

    uint4 u0 = __ldg(&((const uint4*)g_ef)[(long)e0 * DCH + c]);
    uint4 u1 = __ldg(&((const uint4*)g_ef)[(long)e1 * DCH + c]);

    u0.x = h2_as_u(__hmul2(u_as_h2(u0.x), r0));
    u0.y = h2_as_u(__hmul2(u_as_h2(u0.y), r0));
    u0.z = h2_as_u(__hmul2(u_as_h2(u0.z), r0));
    u0.w = h2_as_u(__hmul2(u_as_h2(u0.w), r0));
    u1.x = h2_as_u(__hmul2(u_as_h2(u1.x), r1));
    u1.y = h2_as_u(__hmul2(u_as_h2(u1.y), r1));
    u1.z = h2_as_u(__hmul2(u_as_h2(u1.z), r1));
    u1.w = h2_as_u(__hmul2(u_as_h2(u1.w), r1));

    __half* d0 = &g_h[(long)n0 * D + c * 8];
    __half* d1 = &g_h[(long)n1 * D + c * 8];
    asm volatile("red.global.add.noftz.v4.f16x2 [%0], {%1,%2,%3,%4};"
                 :: "l"(d0), "r"(u0.x), "r"(u0.y), "r"(u0.z), "r"(u0.w) : "memory");
    asm volatile("red.global.add.noftz.v4.f16x2 [%0], {%1,%2,%3,%4};"
                 :: "l"(d1), "r"(u1.x), "r"(u1.y), "r"(u1.z), "r"(u1.w) : "memory");
}

// ---------------------------------------------------------------------------
// K4: final — out = 0.5*x + (0.5/Dn)*h, then restore Dn[node]=0.
// 16 lanes per node (one warp), lane-0 zero-store after all lanes' load.
// ---------------------------------------------------------------------------
__global__ void k_final(const float* __restrict__ x, float* __restrict__ out) {
    int t = blockIdx.x * blockDim.x + threadIdx.x;
    if (t >= N_NODES * DC4) return;
    int node = t >> 4;
    float dnv = g_Dn[node];
    float dn = (dnv > 0.f) ? (0.5f / dnv) : 0.f;

    float4 xv = ((const float4*)x)[t];
    uint2 hu = ((const uint2*)g_h)[t];
    float2 h01 = __half22float2(u_as_h2(hu.x));
    float2 h23 = __half22float2(u_as_h2(hu.y));

    float4 o;
    o.x = 0.5f * xv.x + dn * h01.x;
    o.y = 0.5f * xv.y + dn * h01.y;
    o.z = 0.5f * xv.z + dn * h23.x;
    o.w = 0.5f * xv.w + dn * h23.y;
    ((float4*)out)[t] = o;

    if ((t & 15) == 0) g_Dn[node] = 0.f;   // restore invariant for next call
}

// ---------------------------------------------------------------------------
extern "C" void kernel_launch(void* const* d_in, const int* in_sizes, int n_in,
                              void* d_out, int out_size) {
    const float* x  = (const float*)d_in[0];
    const int*   ni = (const int*)d_in[1];
    const int*   ei = (const int*)d_in[2];
    const float* w  = (const float*)d_in[3];
    float* out = (float*)d_out;

    const int T = 256;
    int stage_threads = MH * DCH;                 // 6.4M threads

    k_prep<<<2048, T>>>(x);
    k_stage1<<<(stage_threads + T - 1) / T, T>>>(ni, ei, w);
    k_recip<<<(N_EDGES + T - 1) / T, T>>>();
    k_stage2<<<(stage_threads + T - 1) / T, T>>>(ni, ei);
    k_final<<<(N_NODES * DC4 + T - 1) / T, T>>>(x, out);
}